// round 4
// baseline (speedup 1.0000x reference)
#include <cuda_runtime.h>

#define NBLK 148
#define TPB  256
#define GSZ  20971520   // 128*512*320
#define NC   163840     // 512*320

// ---------------- static device scratch ----------------
__device__ __align__(16) float d_T0[29 * 1280];     // layer0 gate preact per label (incl bias), perm cols
__device__ __align__(16) float d_B1[1280];          // layer1 bias, perm cols
__device__ __align__(16) float d_W0[320 * 1280];    // w_hh0^T perm: [k][p]
__device__ __align__(16) float d_W1[640 * 1280];    // [w_ih1; w_hh1]^T perm: [k][p]
__device__ __align__(16) float d_A0[2][320 * 512];  // layer0 h, [parity][c][n]
__device__ __align__(16) float d_A1[2][640 * 512];  // layer1 input: rows<320 ys0, rows>=320 h1
__device__ __align__(16) float d_C0[320 * 512];     // layer0 c, [c][n]
__device__ __align__(16) float d_C1[320 * 512];     // layer1 c
__device__ unsigned g_gen, g_cnt, g_tkt;

// ---------------- helpers ----------------
__device__ __forceinline__ unsigned long long splat2(float v) {
    unsigned long long r; asm("mov.b64 %0, {%1, %1};" : "=l"(r) : "f"(v)); return r;
}
__device__ __forceinline__ void fma2(unsigned long long& d, unsigned long long a, unsigned long long b) {
    asm("fma.rn.f32x2 %0, %1, %2, %0;" : "+l"(d) : "l"(a), "l"(b));
}
__device__ __forceinline__ float2 un2(unsigned long long v) {
    float lo, hi; asm("mov.b64 {%0, %1}, %2;" : "=f"(lo), "=f"(hi) : "l"(v));
    return make_float2(lo, hi);
}
__device__ __forceinline__ float sigf(float v)   { return __fdividef(1.0f, 1.0f + __expf(-v)); }
__device__ __forceinline__ float tanhf_(float v) { return __fdividef(2.0f, 1.0f + __expf(-2.0f * v)) - 1.0f; }
__device__ __forceinline__ void cp16(void* dst, const void* src) {
    unsigned d = (unsigned)__cvta_generic_to_shared(dst);
    asm volatile("cp.async.cg.shared.global [%0], [%1], 16;" :: "r"(d), "l"(src));
}
__device__ __forceinline__ unsigned ld_acq(const unsigned* p) {
    unsigned v; asm volatile("ld.acquire.gpu.u32 %0, [%1];" : "=r"(v) : "l"(p) : "memory"); return v;
}
__device__ __forceinline__ void st_rel(unsigned* p, unsigned v) {
    asm volatile("st.release.gpu.u32 [%0], %1;" :: "l"(p), "r"(v) : "memory");
}

// ---------------- prep kernels ----------------
// perm col p: cell = p>>2, gate = p&3; natural j = gate*320 + cell.
__global__ void prep_wt(const float* __restrict__ w_ih, const float* __restrict__ w_hh) {
    const int st = gridDim.x * blockDim.x;
    const int i0 = blockIdx.x * blockDim.x + threadIdx.x;
    for (int i = i0; i < 320 * 1280; i += st) {
        const int k = i / 1280, p = i - k * 1280;
        const int j = (p & 3) * 320 + (p >> 2);
        d_W0[i] = w_hh[j * 320 + k];
    }
    for (int i = i0; i < 640 * 1280; i += st) {
        const int k = i / 1280, p = i - k * 1280;
        const int j = (p & 3) * 320 + (p >> 2);
        d_W1[i] = (k < 320) ? w_ih[409600 + j * 320 + k]
                            : w_hh[409600 + j * 320 + (k - 320)];
    }
}

// T0[v][p] = bias0 + dot(embed[v], w_ih0[j]); v==28 (SOS) -> bias only.
__global__ void prep_t0(const float* __restrict__ emb, const float* __restrict__ w_ih,
                        const float* __restrict__ b_ih, const float* __restrict__ b_hh) {
    const int v = blockIdx.x / 10;
    const int p = (blockIdx.x % 10) * 128 + threadIdx.x;
    const int j = (p & 3) * 320 + (p >> 2);
    float acc = b_ih[j] + b_hh[j];
    if (v < 28) {
        const float* er = emb + v * 320;
        const float* wr = w_ih + j * 320;
#pragma unroll 4
        for (int k = 0; k < 320; k += 4) {
            const float4 e = *reinterpret_cast<const float4*>(er + k);
            const float4 w = *reinterpret_cast<const float4*>(wr + k);
            acc += e.x * w.x + e.y * w.y + e.z * w.z + e.w * w.w;
        }
    }
    d_T0[v * 1280 + p] = acc;
}

__global__ void prep_state(const float* __restrict__ h0, const float* __restrict__ c0,
                           const float* __restrict__ b_ih, const float* __restrict__ b_hh) {
    const int st = gridDim.x * blockDim.x;
    const int i0 = blockIdx.x * blockDim.x + threadIdx.x;
    for (int i = i0; i < NC; i += st) {
        const int n = i / 320, c = i - n * 320;
        d_A0[0][c * 512 + n]         = h0[i];            // layer0 h read at s=0 (parity 0)
        d_A1[1][(320 + c) * 512 + n] = h0[NC + i];       // layer1 h read at s=1 (parity 1)
        d_C0[c * 512 + n] = c0[i];
        d_C1[c * 512 + n] = c0[NC + i];
    }
    for (int i = i0; i < 1280; i += st) {
        const int j = (i & 3) * 320 + (i >> 2);
        d_B1[i] = b_ih[1280 + j] + b_hh[1280 + j];
    }
    if (i0 == 0) { g_gen = 0u; g_cnt = 0u; g_tkt = 0u; }
}

// ---------------- persistent LSTM kernel ----------------
// interval s (0..128): layer0 step s (if s<128) + layer1 step s-1 (if s>=1).
// 320 tickets: [0,160) layer1 tiles (K=640), [160,320) layer0 tiles (K=320).
// tile: 32 batch rows x 128 perm cols (32 cells).
__global__ void __launch_bounds__(TPB, 1)
lstm_pers(const int* __restrict__ x, float* __restrict__ out) {
    __shared__ float sA[2][16 * 32];
    __shared__ float sB[2][16 * 128];
    __shared__ unsigned sh_tk;
    const int tx = threadIdx.x;
    const int lane = tx & 31, wid = tx >> 5;

    for (int s = 0; s < 129; ++s) {
        const int par = s & 1;
        for (;;) {
            __syncthreads();
            if (tx == 0) sh_tk = atomicAdd(&g_tkt, 1u);
            __syncthreads();
            const unsigned tk = sh_tk;
            if (tk >= 320u) break;
            const int lay1 = (tk < 160u);
            if ((s == 0 && lay1) || (s == 128 && !lay1)) continue;

            const int q  = lay1 ? (int)tk : (int)tk - 160;
            const int n0 = (q / 10) * 32;
            const int p0 = (q % 10) * 128;
            const int K  = lay1 ? 640 : 320;
            const float* Wt = lay1 ? d_W1 : d_W0;
            const float* At = lay1 ? d_A1[par] : d_A0[par];
            const int nchunk = K >> 4;

            unsigned long long acc[4][2];
#pragma unroll
            for (int r = 0; r < 4; ++r) { acc[r][0] = 0ull; acc[r][1] = 0ull; }

            // prefetch macro-ish lambda
            auto prefetch = [&](int ch, int buf) {
                const int k0 = ch << 4;
                if (tx < 128) {
                    const int kk = tx >> 3, nn = (tx & 7) * 4;
                    cp16(&sA[buf][kk * 32 + nn], At + (k0 + kk) * 512 + n0 + nn);
                }
#pragma unroll
                for (int it = 0; it < 2; ++it) {
                    const int idx = tx + it * 256;
                    const int kk = idx >> 5, pp = (idx & 31) * 4;
                    cp16(&sB[buf][kk * 128 + pp], Wt + (k0 + kk) * 1280 + p0 + pp);
                }
                asm volatile("cp.async.commit_group;");
            };

            prefetch(0, 0);
            prefetch(1, 1);

            for (int ch = 0; ch < nchunk; ++ch) {
                const int buf = ch & 1;
                if (ch + 1 < nchunk) asm volatile("cp.async.wait_group 1;");
                else                 asm volatile("cp.async.wait_group 0;");
                __syncthreads();
#pragma unroll
                for (int kk = 0; kk < 16; ++kk) {
                    const float4 av = *reinterpret_cast<const float4*>(&sA[buf][kk * 32 + (wid << 2)]);
                    const ulonglong2 bb = *reinterpret_cast<const ulonglong2*>(&sB[buf][kk * 128 + (lane << 2)]);
                    unsigned long long a;
                    a = splat2(av.x); fma2(acc[0][0], a, bb.x); fma2(acc[0][1], a, bb.y);
                    a = splat2(av.y); fma2(acc[1][0], a, bb.x); fma2(acc[1][1], a, bb.y);
                    a = splat2(av.z); fma2(acc[2][0], a, bb.x); fma2(acc[2][1], a, bb.y);
                    a = splat2(av.w); fma2(acc[3][0], a, bb.x); fma2(acc[3][1], a, bb.y);
                }
                __syncthreads();
                if (ch + 2 < nchunk) prefetch(ch + 2, buf);
            }

            // epilogue: full LSTM cell per (row, cell) in registers
            const int cell = (p0 >> 2) + lane;
            float* Cst = lay1 ? d_C1 : d_C0;
            const int u = lay1 ? (s - 1) : s;
#pragma unroll
            for (int r = 0; r < 4; ++r) {
                const int n = n0 + (wid << 2) + r;
                const float2 g01 = un2(acc[r][0]);
                const float2 g23 = un2(acc[r][1]);
                float gi, gf, gg, go;
                if (lay1) {
                    gi = g01.x + d_B1[cell * 4 + 0];
                    gf = g01.y + d_B1[cell * 4 + 1];
                    gg = g23.x + d_B1[cell * 4 + 2];
                    go = g23.y + d_B1[cell * 4 + 3];
                } else {
                    const int lab = x[u * 512 + n];           // 0..28; 28=SOS -> bias row
                    const float* t0 = d_T0 + lab * 1280 + cell * 4;
                    gi = g01.x + t0[0]; gf = g01.y + t0[1];
                    gg = g23.x + t0[2]; go = g23.y + t0[3];
                }
                gi = sigf(gi); gf = sigf(gf); gg = tanhf_(gg); go = sigf(go);
                const int sidx = cell * 512 + n;
                const float c = gf * Cst[sidx] + gi * gg;
                Cst[sidx] = c;
                const float h = go * tanhf_(c);
                if (lay1) {
                    out[u * NC + n * 320 + cell] = h;                     // g output
                    d_A1[par ^ 1][(320 + cell) * 512 + n] = h;            // h1 for next step
                    if (u == 127) {
                        out[GSZ + NC + n * 320 + cell]     = h;           // hg[1]
                        out[GSZ + 3 * NC + n * 320 + cell] = c;           // cg[1]
                    }
                } else {
                    d_A0[par ^ 1][sidx] = h;                              // h0 for next step
                    d_A1[par ^ 1][sidx] = h;                              // ys0 for layer1 next interval
                    if (u == 127) {
                        out[GSZ + n * 320 + cell]          = h;           // hg[0]
                        out[GSZ + 2 * NC + n * 320 + cell] = c;           // cg[0]
                    }
                }
            }
        }

        // ---- grid barrier (release/acquire), last arriver resets ticket ----
        __syncthreads();
        if (tx == 0) {
            __threadfence();
            const unsigned arrived = atomicAdd(&g_cnt, 1u);
            if (arrived == NBLK - 1) {
                g_tkt = 0u;
                g_cnt = 0u;
                __threadfence();
                st_rel(&g_gen, (unsigned)(s + 1));
            } else {
                while (ld_acq(&g_gen) <= (unsigned)s) __nanosleep(40);
            }
        }
        __syncthreads();
    }
}

// ---------------- launcher ----------------
extern "C" void kernel_launch(void* const* d_in, const int* in_sizes, int n_in,
                              void* d_out, int out_size) {
    const int*   x    = (const int*)d_in[0];
    const float* h0   = (const float*)d_in[1];
    const float* c0   = (const float*)d_in[2];
    const float* emb  = (const float*)d_in[3];
    const float* w_ih = (const float*)d_in[4];
    const float* w_hh = (const float*)d_in[5];
    const float* b_ih = (const float*)d_in[6];
    const float* b_hh = (const float*)d_in[7];

    prep_wt<<<512, 256>>>(w_ih, w_hh);
    prep_t0<<<290, 128>>>(emb, w_ih, b_ih, b_hh);
    prep_state<<<256, 256>>>(h0, c0, b_ih, b_hh);
    lstm_pers<<<NBLK, TPB>>>(x, (float*)d_out);
}

// round 5
// speedup vs baseline: 2.6752x; 2.6752x over previous
#include <cuda_runtime.h>

#define NBLK 148
#define TPB  256
#define GSZ  20971520   // 128*512*320
#define NC   163840     // 512*320

// ---------------- static device scratch ----------------
__device__ __align__(16) float d_T0[29 * 1280];     // layer0 gate preact per label (incl bias), perm cols
__device__ __align__(16) float d_B1[1280];          // layer1 bias, perm cols
__device__ __align__(16) float d_W0[320 * 1280];    // w_hh0^T perm: [k][p]
__device__ __align__(16) float d_W1[640 * 1280];    // [w_ih1; w_hh1]^T perm: [k][p]
__device__ __align__(16) float d_A0[2][320 * 512];  // layer0 h, [parity][c][n]
__device__ __align__(16) float d_A1[2][640 * 512];  // layer1 input: rows<320 ys0, rows>=320 h1
__device__ __align__(16) float d_C0[512 * 320];     // layer0 c, [n][c]  (epilogue-coalesced)
__device__ __align__(16) float d_C1[512 * 320];     // layer1 c, [n][c]
__device__ unsigned g_gen, g_cnt;

// ---------------- helpers ----------------
__device__ __forceinline__ unsigned long long splat2(float v) {
    unsigned long long r; asm("mov.b64 %0, {%1, %1};" : "=l"(r) : "f"(v)); return r;
}
__device__ __forceinline__ void fma2(unsigned long long& d, unsigned long long a, unsigned long long b) {
    asm("fma.rn.f32x2 %0, %1, %2, %0;" : "+l"(d) : "l"(a), "l"(b));
}
__device__ __forceinline__ float2 un2(unsigned long long v) {
    float lo, hi; asm("mov.b64 {%0, %1}, %2;" : "=f"(lo), "=f"(hi) : "l"(v));
    return make_float2(lo, hi);
}
__device__ __forceinline__ float sigf(float v)   { return __fdividef(1.0f, 1.0f + __expf(-v)); }
__device__ __forceinline__ float tanhf_(float v) { return __fdividef(2.0f, 1.0f + __expf(-2.0f * v)) - 1.0f; }
__device__ __forceinline__ void cp16(void* dst, const void* src) {
    unsigned d = (unsigned)__cvta_generic_to_shared(dst);
    asm volatile("cp.async.cg.shared.global [%0], [%1], 16;" :: "r"(d), "l"(src));
}
__device__ __forceinline__ unsigned ld_acq(const unsigned* p) {
    unsigned v; asm volatile("ld.acquire.gpu.u32 %0, [%1];" : "=r"(v) : "l"(p) : "memory"); return v;
}
__device__ __forceinline__ void st_rel(unsigned* p, unsigned v) {
    asm volatile("st.release.gpu.u32 [%0], %1;" :: "l"(p), "r"(v) : "memory");
}

// ---------------- prep kernels ----------------
// perm col p: cell = p>>2, gate = p&3; natural j = gate*320 + cell.
__global__ void prep_wt(const float* __restrict__ w_ih, const float* __restrict__ w_hh) {
    const int st = gridDim.x * blockDim.x;
    const int i0 = blockIdx.x * blockDim.x + threadIdx.x;
    for (int i = i0; i < 320 * 1280; i += st) {
        const int k = i / 1280, p = i - k * 1280;
        const int j = (p & 3) * 320 + (p >> 2);
        d_W0[i] = w_hh[j * 320 + k];
    }
    for (int i = i0; i < 640 * 1280; i += st) {
        const int k = i / 1280, p = i - k * 1280;
        const int j = (p & 3) * 320 + (p >> 2);
        d_W1[i] = (k < 320) ? w_ih[409600 + j * 320 + k]
                            : w_hh[409600 + j * 320 + (k - 320)];
    }
}

// T0[v][p] = bias0 + dot(embed[v], w_ih0[j]); v==28 (SOS) -> bias only.
__global__ void prep_t0(const float* __restrict__ emb, const float* __restrict__ w_ih,
                        const float* __restrict__ b_ih, const float* __restrict__ b_hh) {
    const int v = blockIdx.x / 10;
    const int p = (blockIdx.x % 10) * 128 + threadIdx.x;
    const int j = (p & 3) * 320 + (p >> 2);
    float acc = b_ih[j] + b_hh[j];
    if (v < 28) {
        const float* er = emb + v * 320;
        const float* wr = w_ih + j * 320;
#pragma unroll 4
        for (int k = 0; k < 320; k += 4) {
            const float4 e = *reinterpret_cast<const float4*>(er + k);
            const float4 w = *reinterpret_cast<const float4*>(wr + k);
            acc += e.x * w.x + e.y * w.y + e.z * w.z + e.w * w.w;
        }
    }
    d_T0[v * 1280 + p] = acc;
}

__global__ void prep_state(const float* __restrict__ h0, const float* __restrict__ c0,
                           const float* __restrict__ b_ih, const float* __restrict__ b_hh) {
    const int st = gridDim.x * blockDim.x;
    const int i0 = blockIdx.x * blockDim.x + threadIdx.x;
    for (int i = i0; i < NC; i += st) {
        const int n = i / 320, c = i - n * 320;
        d_A0[0][c * 512 + n]         = h0[i];         // layer0 h read at s=0 (parity 0)
        d_A1[1][(320 + c) * 512 + n] = h0[NC + i];    // layer1 h read at s=1 (parity 1)
        d_C0[i] = c0[i];                              // [n][c] natural copy
        d_C1[i] = c0[NC + i];
    }
    for (int i = i0; i < 1280; i += st) {
        const int j = (i & 3) * 320 + (i >> 2);
        d_B1[i] = b_ih[1280 + j] + b_hh[1280 + j];
    }
    if (i0 == 0) { g_gen = 0u; g_cnt = 0u; }
}

// ---------------- persistent LSTM kernel ----------------
// interval s (0..128): layer0 step s (s<128) + layer1 step s-1 (s>=1).
// Static schedule: 80 heavy tiles (layer1, K=640, 2u) -> CTAs 0..79;
// 80 light tiles (layer0, K=320, 1u) -> CTAs 80..147 (first 12 get 2).
// tile: 64 batch rows x 128 perm cols (32 cells); thread: 8 rows x 1 cell.
__global__ void __launch_bounds__(TPB, 1)
lstm_pers(const int* __restrict__ x, float* __restrict__ out) {
    __shared__ __align__(16) float sA[2][16 * 64];    // 8KB
    __shared__ __align__(16) float sB[2][16 * 128];   // 16KB
    float* hstage = &sB[0][0];                        // 32*65 floats, aliases sB post-GEMM
    const int tx = threadIdx.x;
    const int lane = tx & 31, wid = tx >> 5;
    const int b = blockIdx.x;

    for (int s = 0; s < 129; ++s) {
        const int par = s & 1;
        int tiles[2]; int nt = 0;
        if (b < 80) {
            if (s >= 1) tiles[nt++] = b;                       // heavy (layer1)
        } else if (s < 128) {
            const int j = b - 80;
            tiles[nt++] = 80 + j;                              // light (layer0)
            if (j < 12) tiles[nt++] = 80 + 68 + j;
        }

        for (int ti = 0; ti < nt; ++ti) {
            const int tk   = tiles[ti];
            const int lay1 = (tk < 80);
            const int q    = lay1 ? tk : tk - 80;
            const int n0   = (q / 10) * 64;
            const int p0   = (q % 10) * 128;
            const int K    = lay1 ? 640 : 320;
            const float* Wt = lay1 ? d_W1 : d_W0;
            const float* At = lay1 ? d_A1[par] : d_A0[par];
            const int nch  = K >> 4;

            unsigned long long acc[8][2];
#pragma unroll
            for (int r = 0; r < 8; ++r) { acc[r][0] = 0ull; acc[r][1] = 0ull; }

            auto prefetch = [&](int ch, int buf) {
                const int k0 = ch << 4;
                {   // A: 16x64 floats, 1 float4 per thread
                    const int kk = tx >> 4, nn = (tx & 15) * 4;
                    cp16(&sA[buf][kk * 64 + nn], At + (k0 + kk) * 512 + n0 + nn);
                }
#pragma unroll
                for (int it = 0; it < 2; ++it) {  // B: 16x128 floats, 2 float4 per thread
                    const int idx = tx + it * 256;
                    const int kk = idx >> 5, pp = (idx & 31) * 4;
                    cp16(&sB[buf][kk * 128 + pp], Wt + (k0 + kk) * 1280 + p0 + pp);
                }
                asm volatile("cp.async.commit_group;");
            };

            prefetch(0, 0);
            prefetch(1, 1);

            for (int ch = 0; ch < nch; ++ch) {
                const int buf = ch & 1;
                if (ch + 1 < nch) asm volatile("cp.async.wait_group 1;");
                else              asm volatile("cp.async.wait_group 0;");
                __syncthreads();
#pragma unroll
                for (int kk = 0; kk < 16; ++kk) {
                    const float4 a0 = *reinterpret_cast<const float4*>(&sA[buf][kk * 64 + (wid << 3)]);
                    const float4 a1 = *reinterpret_cast<const float4*>(&sA[buf][kk * 64 + (wid << 3) + 4]);
                    const ulonglong2 bb = *reinterpret_cast<const ulonglong2*>(&sB[buf][kk * 128 + (lane << 2)]);
                    unsigned long long a;
                    a = splat2(a0.x); fma2(acc[0][0], a, bb.x); fma2(acc[0][1], a, bb.y);
                    a = splat2(a0.y); fma2(acc[1][0], a, bb.x); fma2(acc[1][1], a, bb.y);
                    a = splat2(a0.z); fma2(acc[2][0], a, bb.x); fma2(acc[2][1], a, bb.y);
                    a = splat2(a0.w); fma2(acc[3][0], a, bb.x); fma2(acc[3][1], a, bb.y);
                    a = splat2(a1.x); fma2(acc[4][0], a, bb.x); fma2(acc[4][1], a, bb.y);
                    a = splat2(a1.y); fma2(acc[5][0], a, bb.x); fma2(acc[5][1], a, bb.y);
                    a = splat2(a1.z); fma2(acc[6][0], a, bb.x); fma2(acc[6][1], a, bb.y);
                    a = splat2(a1.w); fma2(acc[7][0], a, bb.x); fma2(acc[7][1], a, bb.y);
                }
                __syncthreads();
                if (ch + 2 < nch) prefetch(ch + 2, buf);
            }

            // ---- epilogue: LSTM cell update; thread owns 8 rows x 1 cell ----
            const int cell = (p0 >> 2) + lane;
            float* Cst = lay1 ? d_C1 : d_C0;
            const int u = lay1 ? (s - 1) : s;
            float4 bia;
            if (lay1) bia = *reinterpret_cast<const float4*>(&d_B1[cell * 4]);
            float hv[8];
#pragma unroll
            for (int r = 0; r < 8; ++r) {
                const int n = n0 + (wid << 3) + r;
                const float2 g01 = un2(acc[r][0]);
                const float2 g23 = un2(acc[r][1]);
                float gi, gf, gg, go;
                if (lay1) {
                    gi = g01.x + bia.x; gf = g01.y + bia.y;
                    gg = g23.x + bia.z; go = g23.y + bia.w;
                } else {
                    const int lab = x[u * 512 + n];   // 0..28; 28=SOS -> bias-only row
                    const float4 t0 = *reinterpret_cast<const float4*>(&d_T0[lab * 1280 + (cell << 2)]);
                    gi = g01.x + t0.x; gf = g01.y + t0.y;
                    gg = g23.x + t0.z; go = g23.y + t0.w;
                }
                gi = sigf(gi); gf = sigf(gf); gg = tanhf_(gg); go = sigf(go);
                const int ci = n * 320 + cell;        // [n][c] coalesced across lanes
                const float c = gf * Cst[ci] + gi * gg;
                Cst[ci] = c;
                const float h = go * tanhf_(c);
                hv[r] = h;
                if (lay1) {
                    out[u * NC + ci] = h;             // g output, coalesced
                    if (u == 127) { out[GSZ + NC + ci] = h; out[GSZ + 3 * NC + ci] = c; }
                } else {
                    if (u == 127) { out[GSZ + ci] = h; out[GSZ + 2 * NC + ci] = c; }
                }
            }

            // ---- h write transposed [c][n] via padded smem stage (coalesced) ----
            __syncthreads();                           // GEMM smem reads done; sB reusable
#pragma unroll
            for (int r = 0; r < 8; ++r)
                hstage[lane * 65 + (wid << 3) + r] = hv[r];
            __syncthreads();
            {
                const int cell0 = p0 >> 2;
                float* dstA = lay1 ? &d_A1[par ^ 1][(320 + cell0) * 512 + n0]
                                   : &d_A0[par ^ 1][cell0 * 512 + n0];
                float* dstB = lay1 ? nullptr : &d_A1[par ^ 1][cell0 * 512 + n0];
#pragma unroll
                for (int i = tx; i < 2048; i += 256) {
                    const int cl = i >> 6, rw = i & 63;
                    const float v = hstage[cl * 65 + rw];
                    dstA[cl * 512 + rw] = v;
                    if (!lay1) dstB[cl * 512 + rw] = v;  // ys0 feed for layer1
                }
            }
            __syncthreads();                           // protect hstage before next prefetch
        }

        // ---- grid barrier (release/acquire) ----
        __syncthreads();
        if (tx == 0) {
            __threadfence();
            const unsigned arrived = atomicAdd(&g_cnt, 1u);
            if (arrived == NBLK - 1) {
                g_cnt = 0u;
                __threadfence();
                st_rel(&g_gen, (unsigned)(s + 1));
            } else {
                while (ld_acq(&g_gen) <= (unsigned)s) __nanosleep(40);
            }
        }
        __syncthreads();
    }
}

// ---------------- launcher ----------------
extern "C" void kernel_launch(void* const* d_in, const int* in_sizes, int n_in,
                              void* d_out, int out_size) {
    const int*   x    = (const int*)d_in[0];
    const float* h0   = (const float*)d_in[1];
    const float* c0   = (const float*)d_in[2];
    const float* emb  = (const float*)d_in[3];
    const float* w_ih = (const float*)d_in[4];
    const float* w_hh = (const float*)d_in[5];
    const float* b_ih = (const float*)d_in[6];
    const float* b_hh = (const float*)d_in[7];

    prep_wt<<<512, 256>>>(w_ih, w_hh);
    prep_t0<<<290, 128>>>(emb, w_ih, b_ih, b_hh);
    prep_state<<<256, 256>>>(h0, c0, b_ih, b_hh);
    lstm_pers<<<NBLK, TPB>>>(x, (float*)d_out);
}